// round 14
// baseline (speedup 1.0000x reference)
#include <cuda_runtime.h>
#include <cstdint>

#define B_SZ   256
#define F_SZ   128
#define DEPTHD 6
#define C_SZ   100
#define L_SZ   64
#define NTREE  8192
#define KTOT   ((size_t)NTREE * L_SZ)     /* 524288 */
#define NSLICE 148                        /* one CTA per tree-slice */
#define N_PAD  104                        /* C padded: 13 n-tiles of 8 */
#define SST    68                         /* sel smem stride (words) */
#define HST    36                         /* B smem stride (words), 36 mod 32 = 4 */
#define FVS    260                        /* fv smem row stride (floats) */
#define BUFW   (N_PAD * HST + DEPTHD * FVS)   /* words per ring buffer = 5304 */
#define W_SCALE   512.0f
#define W_INV     0.001953125f            /* 1/512 */

/* scratch: fv[m = tree*6+d][b], 49152 x 256 floats = 50.3 MB */
__device__ float g_fv[NTREE * DEPTHD * B_SZ];

/* ---- helpers ---- */
/* pack (lo, hi) floats -> f16x2 reg. PTX: cvt d, a, b => d.lo = b, d.hi = a */
__device__ __forceinline__ uint32_t f2h2(float lo, float hi) {
    uint32_t u; asm("cvt.rn.f16x2.f32 %0, %1, %2;" : "=r"(u) : "f"(hi), "f"(lo)); return u;
}
__device__ __forceinline__ void mma16(float c[4],
                                      uint32_t a0, uint32_t a1, uint32_t a2, uint32_t a3,
                                      uint32_t b0, uint32_t b1) {
    asm volatile(
        "mma.sync.aligned.m16n8k16.row.col.f32.f16.f16.f32 "
        "{%0,%1,%2,%3}, {%4,%5,%6,%7}, {%8,%9}, {%0,%1,%2,%3};"
        : "+f"(c[0]), "+f"(c[1]), "+f"(c[2]), "+f"(c[3])
        : "r"(a0), "r"(a1), "r"(a2), "r"(a3), "r"(b0), "r"(b1));
}

/* ================= kernel 1: selector GEMM + sigmoid (fp16 m16n8k16) ========= */
__global__ void __launch_bounds__(256) sel_fp16(const float* __restrict__ x,
                                                const float* __restrict__ selW,
                                                const float* __restrict__ selb) {
    extern __shared__ uint32_t sm[];
    uint32_t* As = sm;                 /* 128 x SST */
    uint32_t* Bs = sm + 128 * SST;     /* 64 x SST  */

    const int tid = threadIdx.x;
    const int wid = tid >> 5, lane = tid & 31;
    const int g = lane >> 2, tg = lane & 3;
    const int mw = wid & 3, nw = wid >> 2;
    const int row0 = blockIdx.x * 128, col0 = blockIdx.y * 64;

#pragma unroll
    for (int it = 0; it < 16; it++) {
        int e = tid + it * 256;
        int r = e >> 5, q = e & 31;
        float4 v = *(const float4*)(selW + (size_t)(row0 + r) * F_SZ + q * 4);
        uint2 w; w.x = f2h2(v.x, v.y); w.y = f2h2(v.z, v.w);
        *(uint2*)&As[r * SST + q * 2] = w;
    }
#pragma unroll
    for (int it = 0; it < 8; it++) {
        int e = tid + it * 256;
        int r = e >> 5, q = e & 31;
        float4 v = *(const float4*)(x + (size_t)(col0 + r) * F_SZ + q * 4);
        uint2 w; w.x = f2h2(v.x, v.y); w.y = f2h2(v.z, v.w);
        *(uint2*)&Bs[r * SST + q * 2] = w;
    }
    __syncthreads();

    float acc[2][4][4];
#pragma unroll
    for (int mi = 0; mi < 2; mi++)
#pragma unroll
        for (int ni = 0; ni < 4; ni++)
#pragma unroll
            for (int q = 0; q < 4; q++) acc[mi][ni][q] = 0.f;

#pragma unroll
    for (int c = 0; c < 8; c++) {
        uint32_t a[2][4], b[4][2];
#pragma unroll
        for (int mi = 0; mi < 2; mi++) {
            int mb = mw * 32 + mi * 16;
            a[mi][0] = As[(mb + g) * SST + 8 * c + tg];
            a[mi][1] = As[(mb + g + 8) * SST + 8 * c + tg];
            a[mi][2] = As[(mb + g) * SST + 8 * c + tg + 4];
            a[mi][3] = As[(mb + g + 8) * SST + 8 * c + tg + 4];
        }
#pragma unroll
        for (int ni = 0; ni < 4; ni++) {
            int nb = nw * 32 + ni * 8 + g;
            b[ni][0] = Bs[nb * SST + 8 * c + tg];
            b[ni][1] = Bs[nb * SST + 8 * c + tg + 4];
        }
#pragma unroll
        for (int mi = 0; mi < 2; mi++)
#pragma unroll
            for (int ni = 0; ni < 4; ni++)
                mma16(acc[mi][ni], a[mi][0], a[mi][1], a[mi][2], a[mi][3],
                      b[ni][0], b[ni][1]);
    }

#pragma unroll
    for (int mi = 0; mi < 2; mi++) {
        int m = row0 + mw * 32 + mi * 16 + g;
        float b0 = selb[m], b1 = selb[m + 8];
#pragma unroll
        for (int ni = 0; ni < 4; ni++) {
            int bcol = col0 + nw * 32 + ni * 8 + tg * 2;
            float2 v0, v1;
            v0.x = 1.f / (1.f + __expf(-(acc[mi][ni][0] + b0)));
            v0.y = 1.f / (1.f + __expf(-(acc[mi][ni][1] + b0)));
            v1.x = 1.f / (1.f + __expf(-(acc[mi][ni][2] + b1)));
            v1.y = 1.f / (1.f + __expf(-(acc[mi][ni][3] + b1)));
            *(float2*)&g_fv[(size_t)m * B_SZ + bcol] = v0;
            *(float2*)&g_fv[(size_t)(m + 8) * B_SZ + bcol] = v1;
        }
    }
}

/* ================= kernel 2: fused leaf + fp16 GEMM, A-in-registers ==========
 * grid = 148 CTAs, 512 threads, 1 CTA/SM.
 * A-fragments are GENERATED in registers from the leaf product structure:
 *   l bits: b5=d0 b4=d1 b3=d2 b2=d3 b1=d4 b0=d5.
 *   k-chunk c = (d0,d1) -> H[c] = f0 f1; lane tg fixes (d3,d4) -> base;
 *   G[d2][d5] = f2*base*f5. frag half = H[c]*G[..]. No A smem, no A LDS.
 * B (512*W fp16) + raw fv are staged into a 2-buffer smem ring with the R9
 * reg-prefetch pipeline; one syncthreads per tree.
 * 16 warps = 8 mw x 2 nw; warp = 2 m-tiles x {7,6} n-tiles x 4 k-chunks. */
struct Pref {
    float fv3[3];                     /* fv elements tid, tid+512, tid+1024 */
    uint2 w[4];                       /* W slice, pre-converted fp16 (x512) */
};

__device__ __forceinline__ void load_pref(Pref& pr, int t,
                                          const float* __restrict__ outW, int tid) {
    const float* fp = g_fv + (size_t)t * (DEPTHD * B_SZ);
    pr.fv3[0] = fp[tid];
    pr.fv3[1] = fp[tid + 512];
    pr.fv3[2] = fp[tid + 1024];
    const float* wp = outW + (size_t)t * L_SZ;
#pragma unroll
    for (int it = 0; it < 4; it++) {
        int e = tid + it * 512;
        int c = e >> 4, q = e & 15;
        if (e < N_PAD * 16 && c < C_SZ) {
            float4 v = *(const float4*)(wp + (size_t)c * KTOT + q * 4);
            pr.w[it].x = f2h2(v.x * W_SCALE, v.y * W_SCALE);
            pr.w[it].y = f2h2(v.z * W_SCALE, v.w * W_SCALE);
        } else {
            pr.w[it].x = 0u; pr.w[it].y = 0u;
        }
    }
}

__device__ __forceinline__ void store_stage(const Pref& pr, uint32_t* Bb, float* fvs,
                                            int tid) {
    /* ---- raw fv slab: 1536 floats ---- */
#pragma unroll
    for (int k = 0; k < 3; k++) {
        int e = tid + k * 512;
        fvs[(e >> 8) * FVS + (e & 255)] = pr.fv3[k];
    }
    /* ---- W tile: already fp16 in regs; pure STS ---- */
#pragma unroll
    for (int it = 0; it < 4; it++) {
        int e = tid + it * 512;
        if (e < N_PAD * 16) {
            int c = e >> 4, q = e & 15;
            *(uint2*)&Bb[c * HST + q * 2] = pr.w[it];
        }
    }
}

template <int NT>
__device__ __forceinline__ void mma_gen(float acc[2][7][4],
                                        const uint32_t* __restrict__ Bs,
                                        const float* __restrict__ fvs,
                                        int mw, int nw, int g, int tg) {
    /* per-thread leaf factor tables for its 4 rows (mw*32 + 8r + g) */
    float H[4][4], G[4][4];
#pragma unroll
    for (int r = 0; r < 4; r++) {
        int row = mw * 32 + r * 8 + g;
        float p0 = fvs[0 * FVS + row], p1 = fvs[1 * FVS + row];
        float p2 = fvs[2 * FVS + row], p3 = fvs[3 * FVS + row];
        float p4 = fvs[4 * FVS + row], p5 = fvs[5 * FVS + row];
        float f3 = (tg & 2) ? (1.f - p3) : p3;
        float f4 = (tg & 1) ? (1.f - p4) : p4;
        float base = f3 * f4;
        float t2a = p2 * base, t2b = (1.f - p2) * base;
        G[r][0] = t2a * p5; G[r][1] = t2a * (1.f - p5);
        G[r][2] = t2b * p5; G[r][3] = t2b * (1.f - p5);
        H[r][0] = p0 * p1;         H[r][1] = p0 * (1.f - p1);
        H[r][2] = (1.f - p0) * p1; H[r][3] = (1.f - p0) * (1.f - p1);
    }
#pragma unroll
    for (int c = 0; c < 4; c++) {
        uint32_t a[2][4], b[NT][2];
#pragma unroll
        for (int mi = 0; mi < 2; mi++) {
            const int r0 = mi * 2, r1 = mi * 2 + 1;
            a[mi][0] = f2h2(H[r0][c] * G[r0][0], H[r0][c] * G[r0][1]);
            a[mi][1] = f2h2(H[r1][c] * G[r1][0], H[r1][c] * G[r1][1]);
            a[mi][2] = f2h2(H[r0][c] * G[r0][2], H[r0][c] * G[r0][3]);
            a[mi][3] = f2h2(H[r1][c] * G[r1][2], H[r1][c] * G[r1][3]);
        }
#pragma unroll
        for (int ni = 0; ni < NT; ni++) {
            int nb = nw * 56 + ni * 8 + g;
            b[ni][0] = Bs[nb * HST + 8 * c + tg];
            b[ni][1] = Bs[nb * HST + 8 * c + tg + 4];
        }
#pragma unroll
        for (int mi = 0; mi < 2; mi++)
#pragma unroll
            for (int ni = 0; ni < NT; ni++)
                mma16(acc[mi][ni], a[mi][0], a[mi][1], a[mi][2], a[mi][3],
                      b[ni][0], b[ni][1]);
    }
}

__global__ void __launch_bounds__(512, 1) accum_areg(const float* __restrict__ outW,
                                                     const float* __restrict__ outb,
                                                     float* __restrict__ out) {
    extern __shared__ uint32_t sm[];
    /* ring buffer s: [ B: N_PAD*HST words ][ fv: 6*FVS floats ] */
    uint32_t* B0 = sm;
    uint32_t* B1 = sm + BUFW;
    float* F0 = (float*)(sm + N_PAD * HST);
    float* F1 = (float*)(sm + BUFW + N_PAD * HST);

    const int tid = threadIdx.x;
    const int wid = tid >> 5, lane = tid & 31;
    const int g = lane >> 2, tg = lane & 3;
    const int mw = wid & 7, nw = wid >> 3;
    const int slice = blockIdx.x;
    const int t0 = (slice * NTREE) / NSLICE;
    const int t1 = ((slice + 1) * NTREE) / NSLICE;

    float acc[2][7][4];
#pragma unroll
    for (int mi = 0; mi < 2; mi++)
#pragma unroll
        for (int ni = 0; ni < 7; ni++)
#pragma unroll
            for (int q = 0; q < 4; q++) acc[mi][ni][q] = 0.f;

    Pref cur, nxt;
    load_pref(cur, t0, outW, tid);

    int t = t0;
    while (t < t1) {
        /* --- even step: consume cur, prefetch into nxt --- */
        {
            const int buf = (t - t0) & 1;
            store_stage(cur, buf ? B1 : B0, buf ? F1 : F0, tid);
            if (t + 1 < t1) load_pref(nxt, t + 1, outW, tid);
            __syncthreads();
            const uint32_t* Bs = buf ? B1 : B0;
            const float* Fs = buf ? F1 : F0;
            if (nw == 0) mma_gen<7>(acc, Bs, Fs, mw, nw, g, tg);
            else         mma_gen<6>(acc, Bs, Fs, mw, nw, g, tg);
        }
        if (++t >= t1) break;
        /* --- odd step: consume nxt, prefetch into cur --- */
        {
            const int buf = (t - t0) & 1;
            store_stage(nxt, buf ? B1 : B0, buf ? F1 : F0, tid);
            if (t + 1 < t1) load_pref(cur, t + 1, outW, tid);
            __syncthreads();
            const uint32_t* Bs = buf ? B1 : B0;
            const float* Fs = buf ? F1 : F0;
            if (nw == 0) mma_gen<7>(acc, Bs, Fs, mw, nw, g, tg);
            else         mma_gen<6>(acc, Bs, Fs, mw, nw, g, tg);
        }
        ++t;
    }

    /* epilogue: atomicAdd (undo x512 W scale); CTA 0 also adds the bias */
    const int ntiles = nw ? 6 : 7;
    const bool addb = (blockIdx.x == 0);
#pragma unroll
    for (int mi = 0; mi < 2; mi++) {
        int row = mw * 32 + mi * 16 + g;
        float* op0 = out + (size_t)row * C_SZ;
        float* op1 = out + (size_t)(row + 8) * C_SZ;
#pragma unroll
        for (int ni = 0; ni < 7; ni++) {
            if (ni >= ntiles) break;
            int col = nw * 56 + ni * 8 + tg * 2;
            if (col < C_SZ) {
                float bb = addb ? outb[col] : 0.f;
                atomicAdd(op0 + col, acc[mi][ni][0] * W_INV + bb);
                atomicAdd(op1 + col, acc[mi][ni][2] * W_INV + bb);
            }
            if (col + 1 < C_SZ) {
                float bb = addb ? outb[col + 1] : 0.f;
                atomicAdd(op0 + col + 1, acc[mi][ni][1] * W_INV + bb);
                atomicAdd(op1 + col + 1, acc[mi][ni][3] * W_INV + bb);
            }
        }
    }
}

extern "C" void kernel_launch(void* const* d_in, const int* in_sizes, int n_in,
                              void* d_out, int out_size) {
    const float* x    = (const float*)d_in[0];
    const float* selW = (const float*)d_in[1];
    const float* selb = (const float*)d_in[2];
    const float* outW = (const float*)d_in[3];
    const float* outb = (const float*)d_in[4];
    float* out = (float*)d_out;

    cudaMemsetAsync(out, 0, (size_t)out_size * sizeof(float));

    size_t sel_smem = (size_t)(128 + 64) * SST * 4;                  /* 52224 B */
    cudaFuncSetAttribute(sel_fp16, cudaFuncAttributeMaxDynamicSharedMemorySize, (int)sel_smem);
    dim3 g1(384, 4);
    sel_fp16<<<g1, 256, sel_smem>>>(x, selW, selb);

    size_t acc_smem = (size_t)2 * BUFW * 4;                          /* 42432 B */
    cudaFuncSetAttribute(accum_areg, cudaFuncAttributeMaxDynamicSharedMemorySize, (int)acc_smem);
    accum_areg<<<NSLICE, 512, acc_smem>>>(outW, outb, out);
}

// round 15
// speedup vs baseline: 1.0989x; 1.0989x over previous
#include <cuda_runtime.h>
#include <cstdint>

#define B_SZ   256
#define F_SZ   128
#define DEPTHD 6
#define C_SZ   100
#define L_SZ   64
#define NTREE  8192
#define KTOT   ((size_t)NTREE * L_SZ)     /* 524288 */
#define NSLICE 148                        /* one CTA per tree-slice */
#define N_PAD  104                        /* C padded: 13 n-tiles of 8 */
#define SST    68                         /* sel smem stride (words) */
#define HST    36                         /* accum smem stride (words), 36 mod 32 = 4 */
#define W_SCALE   512.0f
#define W_INV     0.001953125f            /* 1/512 */

/* scratch: fv[m = tree*6+d][b], 49152 x 256 floats = 50.3 MB */
__device__ float g_fv[NTREE * DEPTHD * B_SZ];

/* ---- helpers ---- */
/* pack (lo, hi) floats -> f16x2 reg. PTX: cvt d, a, b => d.lo = b, d.hi = a */
__device__ __forceinline__ uint32_t f2h2(float lo, float hi) {
    uint32_t u; asm("cvt.rn.f16x2.f32 %0, %1, %2;" : "=r"(u) : "f"(hi), "f"(lo)); return u;
}
__device__ __forceinline__ void mma16(float c[4],
                                      uint32_t a0, uint32_t a1, uint32_t a2, uint32_t a3,
                                      uint32_t b0, uint32_t b1) {
    asm volatile(
        "mma.sync.aligned.m16n8k16.row.col.f32.f16.f16.f32 "
        "{%0,%1,%2,%3}, {%4,%5,%6,%7}, {%8,%9}, {%0,%1,%2,%3};"
        : "+f"(c[0]), "+f"(c[1]), "+f"(c[2]), "+f"(c[3])
        : "r"(a0), "r"(a1), "r"(a2), "r"(a3), "r"(b0), "r"(b1));
}

/* ================= kernel 1: selector GEMM + sigmoid (fp16 m16n8k16) ========= */
__global__ void __launch_bounds__(256) sel_fp16(const float* __restrict__ x,
                                                const float* __restrict__ selW,
                                                const float* __restrict__ selb) {
    extern __shared__ uint32_t sm[];
    uint32_t* As = sm;                 /* 128 x SST */
    uint32_t* Bs = sm + 128 * SST;     /* 64 x SST  */

    const int tid = threadIdx.x;
    const int wid = tid >> 5, lane = tid & 31;
    const int g = lane >> 2, tg = lane & 3;
    const int mw = wid & 3, nw = wid >> 2;
    const int row0 = blockIdx.x * 128, col0 = blockIdx.y * 64;

#pragma unroll
    for (int it = 0; it < 16; it++) {
        int e = tid + it * 256;
        int r = e >> 5, q = e & 31;
        float4 v = *(const float4*)(selW + (size_t)(row0 + r) * F_SZ + q * 4);
        uint2 w; w.x = f2h2(v.x, v.y); w.y = f2h2(v.z, v.w);
        *(uint2*)&As[r * SST + q * 2] = w;
    }
#pragma unroll
    for (int it = 0; it < 8; it++) {
        int e = tid + it * 256;
        int r = e >> 5, q = e & 31;
        float4 v = *(const float4*)(x + (size_t)(col0 + r) * F_SZ + q * 4);
        uint2 w; w.x = f2h2(v.x, v.y); w.y = f2h2(v.z, v.w);
        *(uint2*)&Bs[r * SST + q * 2] = w;
    }
    __syncthreads();

    float acc[2][4][4];
#pragma unroll
    for (int mi = 0; mi < 2; mi++)
#pragma unroll
        for (int ni = 0; ni < 4; ni++)
#pragma unroll
            for (int q = 0; q < 4; q++) acc[mi][ni][q] = 0.f;

#pragma unroll
    for (int c = 0; c < 8; c++) {
        uint32_t a[2][4], b[4][2];
#pragma unroll
        for (int mi = 0; mi < 2; mi++) {
            int mb = mw * 32 + mi * 16;
            a[mi][0] = As[(mb + g) * SST + 8 * c + tg];
            a[mi][1] = As[(mb + g + 8) * SST + 8 * c + tg];
            a[mi][2] = As[(mb + g) * SST + 8 * c + tg + 4];
            a[mi][3] = As[(mb + g + 8) * SST + 8 * c + tg + 4];
        }
#pragma unroll
        for (int ni = 0; ni < 4; ni++) {
            int nb = nw * 32 + ni * 8 + g;
            b[ni][0] = Bs[nb * SST + 8 * c + tg];
            b[ni][1] = Bs[nb * SST + 8 * c + tg + 4];
        }
#pragma unroll
        for (int mi = 0; mi < 2; mi++)
#pragma unroll
            for (int ni = 0; ni < 4; ni++)
                mma16(acc[mi][ni], a[mi][0], a[mi][1], a[mi][2], a[mi][3],
                      b[ni][0], b[ni][1]);
    }

#pragma unroll
    for (int mi = 0; mi < 2; mi++) {
        int m = row0 + mw * 32 + mi * 16 + g;
        float b0 = selb[m], b1 = selb[m + 8];
#pragma unroll
        for (int ni = 0; ni < 4; ni++) {
            int bcol = col0 + nw * 32 + ni * 8 + tg * 2;
            float2 v0, v1;
            v0.x = 1.f / (1.f + __expf(-(acc[mi][ni][0] + b0)));
            v0.y = 1.f / (1.f + __expf(-(acc[mi][ni][1] + b0)));
            v1.x = 1.f / (1.f + __expf(-(acc[mi][ni][2] + b1)));
            v1.y = 1.f / (1.f + __expf(-(acc[mi][ni][3] + b1)));
            *(float2*)&g_fv[(size_t)m * B_SZ + bcol] = v0;
            *(float2*)&g_fv[(size_t)(m + 8) * B_SZ + bcol] = v1;
        }
    }
}

/* ================= kernel 2: fused leaf + fp16 GEMM, overlapped pipeline =====
 * grid = 148 CTAs, 512 threads, 1 CTA/SM.
 * Top-sync schedule: per iteration [ store_stage(t+1 -> buf^1) ; mma(t <- buf) ;
 * load_pref(t+2) ; sync ].  Staging STS/FMA interleave with mma issue inside
 * each warp; prefetch LDGs get a full tree of latency slack.
 * A = leaf[256 b, 64 l] fp16, B = 512*W[104 c, 64 l] fp16, stride HST=36.
 * 16 warps = 8 mw x 2 nw; warp = 2 m-tiles x {7,6} n-tiles x 4 k-chunks. */
struct Pref {
    float p0, p1, p2, p3, p4, p5;     /* fv for this thread's (b row, lh) */
    float4 w[4];                      /* W slice elements (predicated)     */
};

__device__ __forceinline__ void load_pref(Pref& pr, int t,
                                          const float* __restrict__ outW,
                                          int tid, int b_local) {
    const float* fp = g_fv + (size_t)t * (DEPTHD * B_SZ) + b_local;
    pr.p0 = fp[0];    pr.p1 = fp[256];  pr.p2 = fp[512];
    pr.p3 = fp[768];  pr.p4 = fp[1024]; pr.p5 = fp[1280];
    const float* wp = outW + (size_t)t * L_SZ;
#pragma unroll
    for (int it = 0; it < 4; it++) {
        int e = tid + it * 512;
        int c = e >> 4, q = e & 15;
        if (e < N_PAD * 16 && c < C_SZ)
            pr.w[it] = *(const float4*)(wp + (size_t)c * KTOT + q * 4);
        else
            pr.w[it] = make_float4(0.f, 0.f, 0.f, 0.f);
    }
}

__device__ __forceinline__ void store_stage(const Pref& pr, uint32_t* Ab, uint32_t* Bb,
                                            int tid, int b_local, int lh) {
    /* ---- leaf tile: 2 threads per b row; lh = bit5 of l (d0 bit) ---- */
    {
        float g0 = lh ? (1.f - pr.p0) : pr.p0;
        float a1[2], a2[4], a3[8], a4[16];
        a1[0] = g0 * pr.p1; a1[1] = g0 * (1.f - pr.p1);
#pragma unroll
        for (int i = 0; i < 2; i++) { a2[2*i] = a1[i] * pr.p2; a2[2*i+1] = a1[i] * (1.f - pr.p2); }
#pragma unroll
        for (int i = 0; i < 4; i++) { a3[2*i] = a2[i] * pr.p3; a3[2*i+1] = a2[i] * (1.f - pr.p3); }
#pragma unroll
        for (int i = 0; i < 8; i++) { a4[2*i] = a3[i] * pr.p4; a4[2*i+1] = a3[i] * (1.f - pr.p4); }
        float p5 = pr.p5, q5 = 1.f - pr.p5;
        uint32_t* dst = Ab + b_local * HST + lh * 16;
#pragma unroll
        for (int i = 0; i < 4; i++) {
            uint4 w;
            w.x = f2h2(a4[4*i]     * p5, a4[4*i]     * q5);
            w.y = f2h2(a4[4*i + 1] * p5, a4[4*i + 1] * q5);
            w.z = f2h2(a4[4*i + 2] * p5, a4[4*i + 2] * q5);
            w.w = f2h2(a4[4*i + 3] * p5, a4[4*i + 3] * q5);
            *(uint4*)(dst + i * 4) = w;
        }
    }
    /* ---- W tile ---- */
#pragma unroll
    for (int it = 0; it < 4; it++) {
        int e = tid + it * 512;
        if (e < N_PAD * 16) {
            int c = e >> 4, q = e & 15;
            uint2 w;
            w.x = f2h2(pr.w[it].x * W_SCALE, pr.w[it].y * W_SCALE);
            w.y = f2h2(pr.w[it].z * W_SCALE, pr.w[it].w * W_SCALE);
            *(uint2*)&Bb[c * HST + q * 2] = w;
        }
    }
}

template <int NT>
__device__ __forceinline__ void mma_trees(float acc[2][7][4],
                                          const uint32_t* __restrict__ As,
                                          const uint32_t* __restrict__ Bs,
                                          int mw, int nw, int g, int tg) {
#pragma unroll
    for (int c = 0; c < 4; c++) {
        uint32_t a[2][4], b[NT][2];
#pragma unroll
        for (int mi = 0; mi < 2; mi++) {
            int mb = mw * 32 + mi * 16;
            a[mi][0] = As[(mb + g) * HST + 8 * c + tg];
            a[mi][1] = As[(mb + g + 8) * HST + 8 * c + tg];
            a[mi][2] = As[(mb + g) * HST + 8 * c + tg + 4];
            a[mi][3] = As[(mb + g + 8) * HST + 8 * c + tg + 4];
        }
#pragma unroll
        for (int ni = 0; ni < NT; ni++) {
            int nb = nw * 56 + ni * 8 + g;
            b[ni][0] = Bs[nb * HST + 8 * c + tg];
            b[ni][1] = Bs[nb * HST + 8 * c + tg + 4];
        }
#pragma unroll
        for (int mi = 0; mi < 2; mi++)
#pragma unroll
            for (int ni = 0; ni < NT; ni++)
                mma16(acc[mi][ni], a[mi][0], a[mi][1], a[mi][2], a[mi][3],
                      b[ni][0], b[ni][1]);
    }
}

__global__ void __launch_bounds__(512, 1) accum_512(const float* __restrict__ outW,
                                                    const float* __restrict__ outb,
                                                    float* __restrict__ out) {
    extern __shared__ uint32_t sm[];
    uint32_t* A0 = sm;                        /* 256*HST words */
    uint32_t* A1 = A0 + 256 * HST;
    uint32_t* B0 = A1 + 256 * HST;            /* 104*HST words */
    uint32_t* B1 = B0 + N_PAD * HST;

    const int tid = threadIdx.x;
    const int wid = tid >> 5, lane = tid & 31;
    const int g = lane >> 2, tg = lane & 3;
    const int mw = wid & 7, nw = wid >> 3;
    const int slice = blockIdx.x;
    const int t0 = (slice * NTREE) / NSLICE;
    const int t1 = ((slice + 1) * NTREE) / NSLICE;

    const int b_local = tid >> 1;
    const int lh = tid & 1;

    float acc[2][7][4];
#pragma unroll
    for (int mi = 0; mi < 2; mi++)
#pragma unroll
        for (int ni = 0; ni < 7; ni++)
#pragma unroll
            for (int q = 0; q < 4; q++) acc[mi][ni][q] = 0.f;

    /* prologue: tree t0 -> buf0; prefetch t0+1 */
    Pref cur, nxt;
    load_pref(cur, t0, outW, tid, b_local);
    store_stage(cur, A0, B0, tid, b_local, lh);
    if (t0 + 1 < t1) load_pref(nxt, t0 + 1, outW, tid, b_local);
    __syncthreads();

    int t = t0;
    while (true) {
        /* --- even iter: mma(t <- buf0); stage t+1 -> buf1; pref t+2 --- */
        {
            if (t + 1 < t1) store_stage(nxt, A1, B1, tid, b_local, lh);
            if (nw == 0) mma_trees<7>(acc, A0, B0, mw, nw, g, tg);
            else         mma_trees<6>(acc, A0, B0, mw, nw, g, tg);
            if (t + 2 < t1) load_pref(cur, t + 2, outW, tid, b_local);
            __syncthreads();
        }
        if (++t >= t1) break;
        /* --- odd iter: mma(t <- buf1); stage t+1 -> buf0; pref t+2 --- */
        {
            if (t + 1 < t1) store_stage(cur, A0, B0, tid, b_local, lh);
            if (nw == 0) mma_trees<7>(acc, A1, B1, mw, nw, g, tg);
            else         mma_trees<6>(acc, A1, B1, mw, nw, g, tg);
            if (t + 2 < t1) load_pref(nxt, t + 2, outW, tid, b_local);
            __syncthreads();
        }
        if (++t >= t1) break;
    }

    /* epilogue: atomicAdd (undo x512 W scale); CTA 0 also adds the bias */
    const int ntiles = nw ? 6 : 7;
    const bool addb = (blockIdx.x == 0);
#pragma unroll
    for (int mi = 0; mi < 2; mi++) {
        int row = mw * 32 + mi * 16 + g;
        float* op0 = out + (size_t)row * C_SZ;
        float* op1 = out + (size_t)(row + 8) * C_SZ;
#pragma unroll
        for (int ni = 0; ni < 7; ni++) {
            if (ni >= ntiles) break;
            int col = nw * 56 + ni * 8 + tg * 2;
            if (col < C_SZ) {
                float bb = addb ? outb[col] : 0.f;
                atomicAdd(op0 + col, acc[mi][ni][0] * W_INV + bb);
                atomicAdd(op1 + col, acc[mi][ni][2] * W_INV + bb);
            }
            if (col + 1 < C_SZ) {
                float bb = addb ? outb[col + 1] : 0.f;
                atomicAdd(op0 + col + 1, acc[mi][ni][1] * W_INV + bb);
                atomicAdd(op1 + col + 1, acc[mi][ni][3] * W_INV + bb);
            }
        }
    }
}

extern "C" void kernel_launch(void* const* d_in, const int* in_sizes, int n_in,
                              void* d_out, int out_size) {
    const float* x    = (const float*)d_in[0];
    const float* selW = (const float*)d_in[1];
    const float* selb = (const float*)d_in[2];
    const float* outW = (const float*)d_in[3];
    const float* outb = (const float*)d_in[4];
    float* out = (float*)d_out;

    cudaMemsetAsync(out, 0, (size_t)out_size * sizeof(float));

    size_t sel_smem = (size_t)(128 + 64) * SST * 4;                  /* 52224 B */
    cudaFuncSetAttribute(sel_fp16, cudaFuncAttributeMaxDynamicSharedMemorySize, (int)sel_smem);
    dim3 g1(384, 4);
    sel_fp16<<<g1, 256, sel_smem>>>(x, selW, selb);

    size_t acc_smem = (size_t)(2 * 256 + 2 * N_PAD) * HST * 4;       /* 103680 B */
    cudaFuncSetAttribute(accum_512, cudaFuncAttributeMaxDynamicSharedMemorySize, (int)acc_smem);
    accum_512<<<NSLICE, 512, acc_smem>>>(outW, outb, out);
}